// round 4
// baseline (speedup 1.0000x reference)
#include <cuda_runtime.h>
#include <cstdint>
#include <math.h>

#define SEQ 512
#define BATCH 128
#define INDIM 256
#define HIDDIM 512
#define OUTDIM 256
#define K0 768
#define K1 1024
#define NBLK 128
#define NTHR 256
#define KT 64
#define NT0 12
#define NT1 16
#define TILE_FLOATS (KT*BATCH)      /* 8192 */

#define SM_W0_BYTES (K0*4*16)       /* 49152  */
#define SM_W1_BYTES (K1*4*16)       /* 65536  */
#define SM_IN_OFF   (SM_W0_BYTES + SM_W1_BYTES)      /* 114688 */
#define SMEM_BYTES  (SM_IN_OFF + 2*TILE_FLOATS*4)    /* 180224 */

__device__ float g_xT[(size_t)SEQ*INDIM*BATCH];   /* [t][k][b] */
__device__ float g_h0[2][HIDDIM*BATCH];           /* [phase][j][b] */
__device__ float g_h1[2][HIDDIM*BATCH];
__device__ unsigned g_cnt;
__device__ unsigned g_gen;

typedef unsigned long long ull;

__device__ __forceinline__ ull PK(float x, float y){
    ull r; asm("mov.b64 %0, {%1, %2};" : "=l"(r) : "f"(x), "f"(y)); return r;
}
__device__ __forceinline__ float2 UPK(ull a){
    float2 f; asm("mov.b64 {%0, %1}, %2;" : "=f"(f.x), "=f"(f.y) : "l"(a)); return f;
}
#define FMA2(acc,a,w) asm("fma.rn.f32x2 %0, %1, %2, %0;" : "+l"(acc) : "l"(a), "l"(w))

__device__ __forceinline__ void cpa16(float* dst, const float* src){
    unsigned d = (unsigned)__cvta_generic_to_shared(dst);
    asm volatile("cp.async.cg.shared.global [%0], [%1], 16;" :: "r"(d), "l"(src) : "memory");
}
#define CP_COMMIT() asm volatile("cp.async.commit_group;" ::: "memory")
#define CP_WAIT0()  asm volatile("cp.async.wait_group 0;" ::: "memory")

__device__ __forceinline__ void stage_tile(float* dst, const float* src, int tid){
    #pragma unroll
    for (int i = 0; i < 8; i++){
        int off = (i*NTHR + tid) * 4;
        cpa16(dst + off, src + off);
    }
    CP_COMMIT();
}

__device__ __forceinline__ float sigf(float x){ return 1.0f/(1.0f+expf(-x)); }

__device__ __forceinline__ void grid_sync(){
    __syncthreads();
    if (threadIdx.x == 0){
        volatile unsigned* vg = &g_gen;
        unsigned gen = *vg;
        __threadfence();
        if (atomicAdd(&g_cnt, 1u) == NBLK-1u){
            atomicExch(&g_cnt, 0u);
            __threadfence();
            atomicAdd(&g_gen, 1u);
        } else {
            while (*vg == gen) { __nanosleep(20); }
        }
        __threadfence();
    }
    __syncthreads();
}

/* x [t][b][k] -> g_xT [t][k][b] */
__global__ void transpose_x(const float* __restrict__ x){
    __shared__ float tile[32][33];
    int t = blockIdx.x, k0 = blockIdx.y*32, b0 = blockIdx.z*32;
    const float* src = x + (size_t)t*BATCH*INDIM;
    #pragma unroll
    for (int i = threadIdx.y; i < 32; i += 8)
        tile[i][threadIdx.x] = src[(size_t)(b0+i)*INDIM + k0 + threadIdx.x];
    __syncthreads();
    float* dst = g_xT + (size_t)t*INDIM*BATCH;
    #pragma unroll
    for (int i = threadIdx.y; i < 32; i += 8)
        dst[(size_t)(k0+i)*BATCH + b0 + threadIdx.x] = tile[threadIdx.x][i];
}

__global__ void __launch_bounds__(NTHR, 1) lstm_persist(
    const float* __restrict__ Wg0, const float* __restrict__ bg0,
    const float* __restrict__ Wg1, const float* __restrict__ bg1,
    const float* __restrict__ W_out, const float* __restrict__ b_out,
    float* __restrict__ out)
{
    extern __shared__ char smem[];
    ulonglong2* wS0 = (ulonglong2*)smem;                      /* [(k*4+jl)] = {(wf,wi),(wc,wo)} */
    ulonglong2* wS1 = (ulonglong2*)(smem + SM_W0_BYTES);
    float*      inS = (float*)(smem + SM_IN_OFF);             /* 2 x [KT][BATCH] */

    const int tid = threadIdx.x, bid = blockIdx.x;
    const int jl  = tid >> 6;          /* local unit 0..3 */
    const int p   = tid & 63;          /* batch pair: batches 2p, 2p+1 */
    const int u   = bid*4 + jl;        /* global hidden unit */

    /* ---- weights -> smem, pre-packed gate pairs ---- */
    for (int idx = tid; idx < K0*4; idx += NTHR){
        int k = idx >> 2, uu = bid*4 + (idx & 3);
        float wf = Wg0[(size_t)(0*HIDDIM+uu)*K0 + k];
        float wi = Wg0[(size_t)(1*HIDDIM+uu)*K0 + k];
        float wc = Wg0[(size_t)(2*HIDDIM+uu)*K0 + k];
        float wo = Wg0[(size_t)(3*HIDDIM+uu)*K0 + k];
        wS0[idx] = make_ulonglong2(PK(wf,wi), PK(wc,wo));
    }
    for (int idx = tid; idx < K1*4; idx += NTHR){
        int k = idx >> 2, uu = bid*4 + (idx & 3);
        float wf = Wg1[(size_t)(0*HIDDIM+uu)*K1 + k];
        float wi = Wg1[(size_t)(1*HIDDIM+uu)*K1 + k];
        float wc = Wg1[(size_t)(2*HIDDIM+uu)*K1 + k];
        float wo = Wg1[(size_t)(3*HIDDIM+uu)*K1 + k];
        wS1[idx] = make_ulonglong2(PK(wf,wi), PK(wc,wo));
    }

    const ull b0fi = PK(bg0[u],          bg0[HIDDIM+u]);
    const ull b0co = PK(bg0[2*HIDDIM+u], bg0[3*HIDDIM+u]);
    const ull b1fi = PK(bg1[u],          bg1[HIDDIM+u]);
    const ull b1co = PK(bg1[2*HIDDIM+u], bg1[3*HIDDIM+u]);

    float C0x=0.f,C0y=0.f,C1x=0.f,C1y=0.f;
    float h0x=0.f,h0y=0.f,h1x=0.f,h1y=0.f;

    /* zero this block's slices of both phases (fresh every launch/replay) */
    {
        float2 z = make_float2(0.f, 0.f);
        int o2 = u*BATCH + 2*p;
        *(float2*)(g_h0[0]+o2) = z; *(float2*)(g_h0[1]+o2) = z;
        *(float2*)(g_h1[0]+o2) = z; *(float2*)(g_h1[1]+o2) = z;
    }
    grid_sync();

    const int oo = bid*2 + ((tid >> 6) & 1);     /* output column, valid for tid<128 */
    const size_t OB = (size_t)SEQ*BATCH*OUTDIM;  /* 16777216 */

    for (int t = 0; t < SEQ; t++){
        const int cw = t & 1, pv = cw ^ 1;

        /* ================= layer 0 ================= */
        const float* xb  = g_xT + (size_t)t*INDIM*BATCH;
        const float* h0p = g_h0[pv];
        ull aA=b0fi, aB=b0co, aC=b0fi, aD=b0co;

        stage_tile(inS, xb, tid);
        for (int kt = 0; kt < NT0; kt++){
            CP_WAIT0();
            __syncthreads();
            if (kt+1 < NT0){
                const float* s = (kt+1 < 4) ? xb + (kt+1)*TILE_FLOATS
                                            : h0p + (kt+1-4)*TILE_FLOATS;
                stage_tile(inS + ((kt+1)&1)*TILE_FLOATS, s, tid);
            }
            const ulonglong2* wp = wS0 + kt*KT*4 + jl;
            const float* ip = inS + (kt&1)*TILE_FLOATS + 2*p;
            #pragma unroll 8
            for (int kk = 0; kk < KT; kk++){
                float2 v = *(const float2*)(ip + kk*BATCH);
                ulonglong2 w = wp[kk*4];
                ull a0 = PK(v.x, v.x), a1 = PK(v.y, v.y);
                FMA2(aA, a0, w.x); FMA2(aB, a0, w.y);
                FMA2(aC, a1, w.x); FMA2(aD, a1, w.y);
            }
        }
        {
            float2 fi0=UPK(aA), co0=UPK(aB), fi1=UPK(aC), co1=UPK(aD);
            C0x = sigf(fi0.x)*C0x + sigf(fi0.y)*tanhf(co0.x);
            h0x = sigf(co0.y)*tanhf(C0x);
            C0y = sigf(fi1.x)*C0y + sigf(fi1.y)*tanhf(co1.x);
            h0y = sigf(co1.y)*tanhf(C0y);
            *(float2*)(g_h0[cw] + u*BATCH + 2*p) = make_float2(h0x, h0y);
        }

        grid_sync();   /* the single per-step barrier */

        /* ========= layer 1  (+ fused out[t-1]) ========= */
        const float* h0c = g_h0[cw];
        const float* h1p = g_h1[pv];
        aA=b1fi; aB=b1co; aC=b1fi; aD=b1co;
        ull oacc = 0;

        stage_tile(inS, h0c, tid);
        for (int kt = 0; kt < NT1; kt++){
            CP_WAIT0();
            __syncthreads();
            if (kt+1 < NT1){
                const float* s = (kt+1 < 8) ? h0c + (kt+1)*TILE_FLOATS
                                            : h1p + (kt+1-8)*TILE_FLOATS;
                stage_tile(inS + ((kt+1)&1)*TILE_FLOATS, s, tid);
            }
            const ulonglong2* wp = wS1 + kt*KT*4 + jl;
            const float* ip = inS + (kt&1)*TILE_FLOATS + 2*p;
            #pragma unroll 8
            for (int kk = 0; kk < KT; kk++){
                float2 v = *(const float2*)(ip + kk*BATCH);
                ulonglong2 w = wp[kk*4];
                ull a0 = PK(v.x, v.x), a1 = PK(v.y, v.y);
                FMA2(aA, a0, w.x); FMA2(aB, a0, w.y);
                FMA2(aC, a1, w.x); FMA2(aD, a1, w.y);
            }
            /* out[t-1] rides the h1[t-1] tiles already staged (kt 8..15) */
            if (kt >= 8 && t > 0 && tid < 128){
                const float* wob = W_out + (size_t)oo*HIDDIM + (kt-8)*KT;
                const float* ip2 = inS + (kt&1)*TILE_FLOATS + 2*p;
                #pragma unroll 8
                for (int kk = 0; kk < KT; kk++){
                    float2 v = *(const float2*)(ip2 + kk*BATCH);
                    float w = __ldg(wob + kk);
                    FMA2(oacc, PK(v.x, v.y), PK(w, w));
                }
            }
        }
        {
            float2 fi0=UPK(aA), co0=UPK(aB), fi1=UPK(aC), co1=UPK(aD);
            C1x = sigf(fi0.x)*C1x + sigf(fi0.y)*tanhf(co0.x);
            h1x = sigf(co0.y)*tanhf(C1x);
            C1y = sigf(fi1.x)*C1y + sigf(fi1.y)*tanhf(co1.x);
            h1y = sigf(co1.y)*tanhf(C1y);
            *(float2*)(g_h1[cw] + u*BATCH + 2*p) = make_float2(h1x, h1y);
        }
        if (t > 0 && tid < 128){
            float2 ov = UPK(oacc);
            float bo = b_out[oo];
            size_t ob = ((size_t)(t-1)*BATCH + 2*p)*OUTDIM + oo;
            out[ob]          = ov.x + bo;
            out[ob + OUTDIM] = ov.y + bo;
        }
    }

    grid_sync();
    /* out[SEQ-1] */
    if (tid < 128){
        ull oacc = 0;
        const float* h1f = g_h1[(SEQ-1)&1];
        const float* wob = W_out + (size_t)oo*HIDDIM;
        #pragma unroll 4
        for (int j = 0; j < HIDDIM; j++){
            float2 v = __ldcg((const float2*)(h1f + j*BATCH + 2*p));
            float w = __ldg(wob + j);
            FMA2(oacc, PK(v.x, v.y), PK(w, w));
        }
        float2 ov = UPK(oacc);
        float bo = b_out[oo];
        size_t ob = ((size_t)(SEQ-1)*BATCH + 2*p)*OUTDIM + oo;
        out[ob]          = ov.x + bo;
        out[ob + OUTDIM] = ov.y + bo;
    }
    /* final states: [B][HID] each, order h_0, C_0, h_1, C_1 */
    {
        size_t r0 = (size_t)(2*p)*HIDDIM + u;
        size_t r1 = (size_t)(2*p+1)*HIDDIM + u;
        out[OB          + r0] = h0x;  out[OB          + r1] = h0y;
        out[OB +  65536 + r0] = C0x;  out[OB +  65536 + r1] = C0y;
        out[OB + 131072 + r0] = h1x;  out[OB + 131072 + r1] = h1y;
        out[OB + 196608 + r0] = C1x;  out[OB + 196608 + r1] = C1y;
    }
}

extern "C" void kernel_launch(void* const* d_in, const int* in_sizes, int n_in,
                              void* d_out, int out_size)
{
    (void)in_sizes; (void)n_in; (void)out_size;
    const float* x     = (const float*)d_in[0];
    const float* Wg0   = (const float*)d_in[1];
    const float* bg0   = (const float*)d_in[2];
    const float* Wg1   = (const float*)d_in[3];
    const float* bg1   = (const float*)d_in[4];
    const float* W_out = (const float*)d_in[5];
    const float* b_out = (const float*)d_in[6];

    cudaFuncSetAttribute(lstm_persist,
                         cudaFuncAttributeMaxDynamicSharedMemorySize, SMEM_BYTES);

    transpose_x<<<dim3(SEQ, INDIM/32, BATCH/32), dim3(32, 8)>>>(x);
    lstm_persist<<<NBLK, NTHR, SMEM_BYTES>>>(Wg0, bg0, Wg1, bg1, W_out, b_out,
                                             (float*)d_out);
}